// round 12
// baseline (speedup 1.0000x reference)
#include <cuda_runtime.h>
#include <cstdint>

// ===========================================================================
// Problem constants
// ===========================================================================
namespace {
constexpr int kB  = 2;
constexpr int kS  = 2048;
constexpr int kD  = 1024;
constexpr int kH  = 16;
constexpr int kDK = 64;
constexpr int kBH = kB * kH;        // 32
constexpr int kBS = kB * kS;        // 4096
constexpr int kNRows = kBH * kS;    // 65536

// proj smem: Ah/Al/Bh/Bl [128 rows][36 floats]
constexpr int kPRS   = 36;
constexpr int kPTile = 128 * kPRS;
constexpr int kPSmem = 4 * kPTile * 4;             // 73728 bytes

// scores smem: Qh/Ql [128][68] + Kh/Kl [64][68]
constexpr int kQRS   = 68;
constexpr int kQTile = 128 * kQRS;
constexpr int kKTile = 64 * kQRS;
constexpr int kSSmem = (2 * kQTile + 2 * kKTile) * 4;   // 104448 bytes

// out smem: Ph/Pl [128][68] + Vh/Vl [64][72]
constexpr int kORS    = 68;
constexpr int kOVS    = 72;
constexpr int kOPTile = 128 * kORS;
constexpr int kOVTile = 64 * kOVS;
constexpr int kOSmem  = (2 * kOPTile + 2 * kOVTile) * 4; // 106496 bytes
}

// Scratch (allocation-free rule: __device__ globals)
__device__ float g_q [kBH * kS * kDK];   // 16 MB
__device__ float g_kr[kBH * kS * kDK];   // 16 MB (k_proj + r_proj)
__device__ float g_v [kBH * kS * kDK];   // 16 MB
__device__ float g_rinv[kNRows];

// ===========================================================================
// helpers (arch-neutral PTX, valid on sm_100 target)
// ===========================================================================
__device__ __forceinline__ void split_tf32(float x, uint32_t& hi, uint32_t& lo) {
    uint32_t h;
    asm("cvt.rna.tf32.f32 %0, %1;" : "=r"(h) : "f"(x));
    float lf = x - __uint_as_float(h);
    uint32_t l;
    asm("cvt.rna.tf32.f32 %0, %1;" : "=r"(l) : "f"(lf));
    hi = h; lo = l;
}

// D += A(tf32) * B(tf32); m16n8k8, A row-major, B col-major.
__device__ __forceinline__ void mma_m16n8k8_tf32(float* d, const uint32_t* a,
                                                 const uint32_t* b) {
    asm volatile(
        "mma.sync.aligned.m16n8k8.row.col.f32.tf32.tf32.f32 "
        "{%0,%1,%2,%3}, {%4,%5,%6,%7}, {%8,%9}, {%0,%1,%2,%3};"
        : "+f"(d[0]), "+f"(d[1]), "+f"(d[2]), "+f"(d[3])
        : "r"(a[0]), "r"(a[1]), "r"(a[2]), "r"(a[3]), "r"(b[0]), "r"(b[1]));
}

__device__ __forceinline__ void ldsm_x4(uint32_t* r, uint32_t saddr) {
    asm volatile("ldmatrix.sync.aligned.m8n8.x4.shared.b16 {%0,%1,%2,%3}, [%4];"
        : "=r"(r[0]), "=r"(r[1]), "=r"(r[2]), "=r"(r[3]) : "r"(saddr));
}
__device__ __forceinline__ void ldsm_x2(uint32_t* r, uint32_t saddr) {
    asm volatile("ldmatrix.sync.aligned.m8n8.x2.shared.b16 {%0,%1}, [%2];"
        : "=r"(r[0]), "=r"(r[1]) : "r"(saddr));
}
__device__ __forceinline__ uint32_t smem_u32(const void* p) {
    return (uint32_t)__cvta_generic_to_shared(p);
}

// ===========================================================================
// Projection GEMM via mma.sync tf32x3 + ldmatrix. (R11 verbatim, ~690us/3)
// ===========================================================================
__global__ __launch_bounds__(256) void proj_mma_kernel(
    const float* __restrict__ X1, const float* __restrict__ W1, const float* __restrict__ b1,
    const float* __restrict__ X2, const float* __restrict__ W2, const float* __restrict__ b2,
    int dst_sel, int ns)
{
    extern __shared__ uint32_t smem_u[];
    uint32_t* Ah = smem_u;
    uint32_t* Al = smem_u + kPTile;
    uint32_t* Bh = smem_u + 2 * kPTile;
    uint32_t* Bl = smem_u + 3 * kPTile;
    const uint32_t ah_b = smem_u32(Ah), al_b = smem_u32(Al);
    const uint32_t bh_b = smem_u32(Bh), bl_b = smem_u32(Bl);

    const int tid   = threadIdx.x;
    const int wid   = tid >> 5;
    const int lane  = tid & 31;
    const int gid   = lane >> 2;
    const int tid4  = lane & 3;
    const int wm    = (wid >> 2) * 64;
    const int wn    = (wid & 3) * 32;
    const int m0    = blockIdx.y * 128;
    const int n0    = blockIdx.x * 128;

    const int a_row = lane & 15;
    const int a_ko  = ((lane >> 4) & 1) << 2;
    const int b_row = lane & 7;
    const int b_ko  = ((lane >> 3) & 1) << 2;

    float acc[4][4][4];
#pragma unroll
    for (int mt = 0; mt < 4; ++mt)
#pragma unroll
        for (int nt = 0; nt < 4; ++nt)
#pragma unroll
            for (int f = 0; f < 4; ++f) acc[mt][nt][f] = 0.f;

    for (int s = 0; s < ns; ++s) {
        const float* __restrict__ X = (s < 32) ? X1 : X2;
        const float* __restrict__ W = (s < 32) ? W1 : W2;
        const int k0 = (s & 31) * 32;

        float4 xa[4], wb[4];
#pragma unroll
        for (int i = 0; i < 4; ++i) {
            const int idx = tid + 256 * i;
            const int row = idx >> 3;
            const int c4  = (idx & 7) * 4;
            xa[i] = *reinterpret_cast<const float4*>(&X[(size_t)(m0 + row) * kD + k0 + c4]);
            wb[i] = *reinterpret_cast<const float4*>(&W[(size_t)(n0 + row) * kD + k0 + c4]);
        }
        __syncthreads();
#pragma unroll
        for (int i = 0; i < 4; ++i) {
            const int idx = tid + 256 * i;
            const int row = idx >> 3;
            const int c4  = (idx & 7) * 4;
            const float* xv = reinterpret_cast<const float*>(&xa[i]);
            const float* wv = reinterpret_cast<const float*>(&wb[i]);
#pragma unroll
            for (int j = 0; j < 4; ++j) {
                uint32_t h, l;
                split_tf32(xv[j], h, l);
                Ah[row * kPRS + c4 + j] = h;
                Al[row * kPRS + c4 + j] = l;
                split_tf32(wv[j], h, l);
                Bh[row * kPRS + c4 + j] = h;
                Bl[row * kPRS + c4 + j] = l;
            }
        }
        __syncthreads();

#pragma unroll
        for (int kk = 0; kk < 4; ++kk) {
            const int kb = kk * 8;

            uint32_t bhf[4][2], blf[4][2];
#pragma unroll
            for (int nt = 0; nt < 4; ++nt) {
                const uint32_t off =
                    (uint32_t)(((wn + nt * 8 + b_row) * kPRS + kb + b_ko) * 4);
                ldsm_x2(bhf[nt], bh_b + off);
                ldsm_x2(blf[nt], bl_b + off);
            }

#pragma unroll
            for (int mt = 0; mt < 4; ++mt) {
                const uint32_t off =
                    (uint32_t)(((wm + mt * 16 + a_row) * kPRS + kb + a_ko) * 4);
                uint32_t ah[4], al[4];
                ldsm_x4(ah, ah_b + off);
                ldsm_x4(al, al_b + off);
#pragma unroll
                for (int nt = 0; nt < 4; ++nt) {
                    mma_m16n8k8_tf32(acc[mt][nt], ah, bhf[nt]);
                    mma_m16n8k8_tf32(acc[mt][nt], ah, blf[nt]);
                    mma_m16n8k8_tf32(acc[mt][nt], al, bhf[nt]);
                }
            }
        }
    }

    float* __restrict__ dst = (dst_sel == 0) ? g_q : (dst_sel == 1) ? g_kr : g_v;
#pragma unroll
    for (int nt = 0; nt < 4; ++nt) {
        const int e  = n0 + wn + nt * 8 + 2 * tid4;
        const int h  = e >> 6;
        const int dk = e & 63;
        float2 bb;
        bb.x = b1[e];     bb.y = b1[e + 1];
        if (X2) { bb.x += b2[e]; bb.y += b2[e + 1]; }
#pragma unroll
        for (int mt = 0; mt < 4; ++mt) {
#pragma unroll
            for (int half = 0; half < 2; ++half) {
                const int gm   = m0 + wm + mt * 16 + gid + half * 8;
                const int bidx = gm >> 11;
                const int srow = gm & (kS - 1);
                float2 o;
                o.x = acc[mt][nt][half * 2 + 0] + bb.x;
                o.y = acc[mt][nt][half * 2 + 1] + bb.y;
                *reinterpret_cast<float2*>(
                    &dst[(((size_t)bidx * kH + h) * kS + srow) * kDK + dk]) = o;
            }
        }
    }
}

// ===========================================================================
// Fused scores + softmax numerator + row sums via mma.sync tf32x3 + ldmatrix.
// (R11 verbatim, measured 489us)
// ===========================================================================
__global__ __launch_bounds__(256, 2) void scores_mma_kernel(const int* __restrict__ mask,
                                                            float* __restrict__ p)
{
    extern __shared__ uint32_t smem_u[];
    uint32_t* Qh = smem_u;
    uint32_t* Ql = smem_u + kQTile;
    uint32_t* Kh = smem_u + 2 * kQTile;
    uint32_t* Kl = smem_u + 2 * kQTile + kKTile;
    const uint32_t qh_b = smem_u32(Qh), ql_b = smem_u32(Ql);
    const uint32_t kh_b = smem_u32(Kh), kl_b = smem_u32(Kl);
    __shared__ float rs[128];

    const int tid   = threadIdx.x;
    const int wid   = tid >> 5;
    const int lane  = tid & 31;
    const int gid   = lane >> 2;
    const int tid4  = lane & 3;
    const int wm    = (wid >> 2) * 64;
    const int wn    = (wid & 3) * 16;
    const int bh    = blockIdx.y;
    const int m0    = blockIdx.x * 128;
    const int b_    = bh >> 4;
    const float scale = 0.125f;

    const int a_row = lane & 15;
    const int a_ko  = ((lane >> 4) & 1) << 2;
    const int b_row = lane & 7;
    const int b_ko  = ((lane >> 3) & 1) << 2;

    const float* __restrict__ Q  = g_q  + (size_t)bh * kS * kDK;
    const float* __restrict__ KR = g_kr + (size_t)bh * kS * kDK;

    if (tid < 128) rs[tid] = 0.f;

    for (int i = tid; i < 128 * 16; i += 256) {
        const int row = i >> 4;
        const int kq  = (i & 15) * 4;
        float4 v = *reinterpret_cast<const float4*>(&Q[(size_t)(m0 + row) * kDK + kq]);
        const float* vv = reinterpret_cast<const float*>(&v);
#pragma unroll
        for (int j = 0; j < 4; ++j) {
            uint32_t h, l;
            split_tf32(vv[j], h, l);
            Qh[row * kQRS + kq + j] = h;
            Ql[row * kQRS + kq + j] = l;
        }
    }

    float rsum[4][2];
#pragma unroll
    for (int mt = 0; mt < 4; ++mt) { rsum[mt][0] = 0.f; rsum[mt][1] = 0.f; }

    for (int nb = 0; nb < kS; nb += 64) {
        __syncthreads();
        for (int i = tid; i < 64 * 16; i += 256) {
            const int n  = i >> 4;
            const int kq = (i & 15) * 4;
            float4 v = *reinterpret_cast<const float4*>(&KR[(size_t)(nb + n) * kDK + kq]);
            const float* vv = reinterpret_cast<const float*>(&v);
#pragma unroll
            for (int j = 0; j < 4; ++j) {
                uint32_t h, l;
                split_tf32(vv[j], h, l);
                Kh[n * kQRS + kq + j] = h;
                Kl[n * kQRS + kq + j] = l;
            }
        }
        __syncthreads();

        float acc[4][2][4];
#pragma unroll
        for (int mt = 0; mt < 4; ++mt)
#pragma unroll
            for (int nt = 0; nt < 2; ++nt)
#pragma unroll
                for (int f = 0; f < 4; ++f) acc[mt][nt][f] = 0.f;

#pragma unroll
        for (int kk = 0; kk < 8; ++kk) {
            const int kb = kk * 8;

            uint32_t bhf[2][2], blf[2][2];
#pragma unroll
            for (int nt = 0; nt < 2; ++nt) {
                const uint32_t off =
                    (uint32_t)(((wn + nt * 8 + b_row) * kQRS + kb + b_ko) * 4);
                ldsm_x2(bhf[nt], kh_b + off);
                ldsm_x2(blf[nt], kl_b + off);
            }

#pragma unroll
            for (int mt = 0; mt < 4; ++mt) {
                const uint32_t off =
                    (uint32_t)(((wm + mt * 16 + a_row) * kQRS + kb + a_ko) * 4);
                uint32_t ah[4], al[4];
                ldsm_x4(ah, qh_b + off);
                ldsm_x4(al, ql_b + off);
#pragma unroll
                for (int nt = 0; nt < 2; ++nt) {
                    mma_m16n8k8_tf32(acc[mt][nt], ah, bhf[nt]);
                    mma_m16n8k8_tf32(acc[mt][nt], ah, blf[nt]);
                    mma_m16n8k8_tf32(acc[mt][nt], al, bhf[nt]);
                }
            }
        }

#pragma unroll
        for (int mt = 0; mt < 4; ++mt) {
#pragma unroll
            for (int nt = 0; nt < 2; ++nt) {
                const int sk = nb + wn + nt * 8 + 2 * tid4;
#pragma unroll
                for (int half = 0; half < 2; ++half) {
                    const int sq = m0 + wm + mt * 16 + gid + half * 8;
                    int2 mm = *reinterpret_cast<const int2*>(
                        &mask[((size_t)b_ * kS + sq) * kS + sk]);
                    const float f0 = acc[mt][nt][half * 2 + 0] * scale;
                    const float f1 = acc[mt][nt][half * 2 + 1] * scale;
                    float2 e;
                    e.x = mm.x ? __expf(f0) : 0.f;
                    e.y = mm.y ? __expf(f1) : 0.f;
                    *reinterpret_cast<float2*>(
                        &p[((size_t)bh * kS + sq) * kS + sk]) = e;
                    rsum[mt][half] += e.x + e.y;
                }
            }
        }
    }

    __syncthreads();
#pragma unroll
    for (int mt = 0; mt < 4; ++mt) {
#pragma unroll
        for (int half = 0; half < 2; ++half) {
            float s = rsum[mt][half];
            s += __shfl_xor_sync(0xffffffffu, s, 1);
            s += __shfl_xor_sync(0xffffffffu, s, 2);
            if (tid4 == 0)
                atomicAdd(&rs[wm + mt * 16 + gid + half * 8], s);
        }
    }
    __syncthreads();
    if (tid < 128) g_rinv[bh * kS + m0 + tid] = 1.0f / rs[tid];
}

// ===========================================================================
// out = p @ v via mma.sync tf32x3 + ldmatrix (A side); V kept k-major,
// B fragments via conflict-free scalar LDS (stride 72). Normalizes p on
// load, writes final p back, accumulates across all 32 k-chunks.
// grid (S/128, BH), 256 threads, dynamic smem kOSmem, 2 CTAs/SM.
// ===========================================================================
__global__ __launch_bounds__(256, 2) void out_mma_kernel(float* __restrict__ p,
                                                         float* __restrict__ out)
{
    extern __shared__ uint32_t smem_u[];
    uint32_t* Ph = smem_u;                             // [128][68]
    uint32_t* Pl = smem_u + kOPTile;
    uint32_t* Vh = smem_u + 2 * kOPTile;               // [64][72]
    uint32_t* Vl = smem_u + 2 * kOPTile + kOVTile;
    const uint32_t ph_b = smem_u32(Ph), pl_b = smem_u32(Pl);
    __shared__ float s_inv[128];

    const int tid   = threadIdx.x;
    const int wid   = tid >> 5;
    const int lane  = tid & 31;
    const int gid   = lane >> 2;
    const int tid4  = lane & 3;
    const int wm    = (wid >> 2) * 64;     // 0 / 64
    const int wn    = (wid & 3) * 16;      // 0/16/32/48
    const int bh    = blockIdx.y;
    const int m0    = blockIdx.x * 128;

    const int a_row = lane & 15;
    const int a_ko  = ((lane >> 4) & 1) << 2;

    if (tid < 128) s_inv[tid] = g_rinv[bh * kS + m0 + tid];
    __syncthreads();

    float acc[4][2][4];                    // persists across all k-chunks
#pragma unroll
    for (int mt = 0; mt < 4; ++mt)
#pragma unroll
        for (int nt = 0; nt < 2; ++nt)
#pragma unroll
            for (int f = 0; f < 4; ++f) acc[mt][nt][f] = 0.f;

    float* __restrict__ prow = p + (size_t)bh * kS * kS + (size_t)m0 * kS;
    const float* __restrict__ V = g_v + (size_t)bh * kS * kDK;

    for (int k0 = 0; k0 < kS; k0 += 64) {
        __syncthreads();   // previous chunk's fragment reads done
        // ---- p tile: normalize, split into Ph/Pl [m][k], write p back ----
        for (int i = tid; i < 128 * 16; i += 256) {
            const int row = i >> 4;
            const int kq  = (i & 15) * 4;
            const float iv = s_inv[row];
            float4 x = *reinterpret_cast<const float4*>(&prow[(size_t)row * kS + k0 + kq]);
            x.x *= iv; x.y *= iv; x.z *= iv; x.w *= iv;
            *reinterpret_cast<float4*>(&prow[(size_t)row * kS + k0 + kq]) = x;
            const float* xv = reinterpret_cast<const float*>(&x);
#pragma unroll
            for (int j = 0; j < 4; ++j) {
                uint32_t h, l;
                split_tf32(xv[j], h, l);
                Ph[row * kORS + kq + j] = h;
                Pl[row * kORS + kq + j] = l;
            }
        }
        // ---- V tile: split into Vh/Vl [k][n] stride 72 ----
        for (int i = tid; i < 64 * 16; i += 256) {
            const int vk = i >> 4;
            const int vn = (i & 15) * 4;
            float4 v = *reinterpret_cast<const float4*>(&V[(size_t)(k0 + vk) * kDK + vn]);
            const float* vv = reinterpret_cast<const float*>(&v);
#pragma unroll
            for (int j = 0; j < 4; ++j) {
                uint32_t h, l;
                split_tf32(vv[j], h, l);
                Vh[vk * kOVS + vn + j] = h;
                Vl[vk * kOVS + vn + j] = l;
            }
        }
        __syncthreads();

        // ---- 8 k8-steps ----
#pragma unroll
        for (int kk = 0; kk < 8; ++kk) {
            const int kb = kk * 8;

            // B fragments: scalar LDS from k-major V, banks 8*tid4+gid (free)
            uint32_t bhf[2][2], blf[2][2];
#pragma unroll
            for (int nt = 0; nt < 2; ++nt) {
                const int n = wn + nt * 8 + gid;
                bhf[nt][0] = Vh[(kb + tid4) * kOVS + n];
                bhf[nt][1] = Vh[(kb + tid4 + 4) * kOVS + n];
                blf[nt][0] = Vl[(kb + tid4) * kOVS + n];
                blf[nt][1] = Vl[(kb + tid4 + 4) * kOVS + n];
            }

#pragma unroll
            for (int mt = 0; mt < 4; ++mt) {
                const uint32_t off =
                    (uint32_t)(((wm + mt * 16 + a_row) * kORS + kb + a_ko) * 4);
                uint32_t ah[4], al[4];
                ldsm_x4(ah, ph_b + off);
                ldsm_x4(al, pl_b + off);
#pragma unroll
                for (int nt = 0; nt < 2; ++nt) {
                    mma_m16n8k8_tf32(acc[mt][nt], ah, bhf[nt]);
                    mma_m16n8k8_tf32(acc[mt][nt], ah, blf[nt]);
                    mma_m16n8k8_tf32(acc[mt][nt], al, bhf[nt]);
                }
            }
        }
    }

    // ---- epilogue: write out (B,H,S,DK) ----
    float* __restrict__ orow = out + (size_t)bh * kS * kDK;
#pragma unroll
    for (int mt = 0; mt < 4; ++mt) {
#pragma unroll
        for (int nt = 0; nt < 2; ++nt) {
            const int dk = wn + nt * 8 + 2 * tid4;
#pragma unroll
            for (int half = 0; half < 2; ++half) {
                const int m = m0 + wm + mt * 16 + gid + half * 8;
                float2 o;
                o.x = acc[mt][nt][half * 2 + 0];
                o.y = acc[mt][nt][half * 2 + 1];
                *reinterpret_cast<float2*>(&orow[(size_t)m * kDK + dk]) = o;
            }
        }
    }
}

// ===========================================================================
extern "C" void kernel_launch(void* const* d_in, const int* in_sizes, int n_in,
                              void* d_out, int out_size)
{
    (void)in_sizes; (void)n_in; (void)out_size;
    const float* query = (const float*)d_in[0];
    const float* key   = (const float*)d_in[1];
    const float* value = (const float*)d_in[2];
    const float* r     = (const float*)d_in[3];
    const int*   mask  = (const int*)  d_in[4];
    const float* Wq = (const float*)d_in[5];  const float* bq = (const float*)d_in[6];
    const float* Wk = (const float*)d_in[7];  const float* bk = (const float*)d_in[8];
    const float* Wv = (const float*)d_in[9];  const float* bv = (const float*)d_in[10];
    const float* Wr = (const float*)d_in[11]; const float* br = (const float*)d_in[12];

    float* out = (float*)d_out;                          // (B,H,S,DK)
    float* p   = out + (size_t)kBH * kS * kDK;           // (B,H,S,S)

    cudaFuncSetAttribute(proj_mma_kernel,
                         cudaFuncAttributeMaxDynamicSharedMemorySize, kPSmem);
    cudaFuncSetAttribute(scores_mma_kernel,
                         cudaFuncAttributeMaxDynamicSharedMemorySize, kSSmem);
    cudaFuncSetAttribute(out_mma_kernel,
                         cudaFuncAttributeMaxDynamicSharedMemorySize, kOSmem);

    dim3 pgrid(kD / 128, kBS / 128);                     // (8, 32)
    proj_mma_kernel<<<pgrid, 256, kPSmem>>>(query, Wq, bq, nullptr, nullptr, nullptr, 0, 32);
    proj_mma_kernel<<<pgrid, 256, kPSmem>>>(key,   Wk, bk, r, Wr, br, 1, 64);  // kr
    proj_mma_kernel<<<pgrid, 256, kPSmem>>>(value, Wv, bv, nullptr, nullptr, nullptr, 2, 32);

    dim3 sgrid(kS / 128, kBH);                           // (16, 32)
    scores_mma_kernel<<<sgrid, 256, kSSmem>>>(mask, p);

    dim3 ogrid(kS / 128, kBH);                           // (16, 32)
    out_mma_kernel<<<ogrid, 256, kOSmem>>>(p, out);
}